// round 1
// baseline (speedup 1.0000x reference)
#include <cuda_runtime.h>
#include <math.h>

// ---------------------------------------------------------------------------
// Encoder_51582557225690 : 8-layer beacon/forget memory transformer, fp32.
// L=8 D=1024 H=16 HD=64 S=1024 M=128 F=2048 B=1
// Key trick: scan output is the carry ENTERING each layer -> layer 7 compute
// is skipped entirely (only its entry state is recorded).
// ---------------------------------------------------------------------------

#define DD    1024
#define HH    16
#define HDIM  64
#define SS    1024
#define MM    128
#define LL    8
#define FF    2048
#define NCAT  1280   /* S + 2M rows in the residual stream            */
#define NKR   1408   /* M(mem) + S(hid) + M(beacon k) + M(forget k)   */
#define NPOS  1280

// ------------------------- device scratch (no allocs) ----------------------
__device__ float g_cat [NCAT * DD];
__device__ float g_x   [NCAT * DD];
__device__ float g_q   [NCAT * DD];
__device__ float g_k   [NKR  * DD];
__device__ float g_v   [NKR  * DD];
__device__ float g_attn[NCAT * DD];
__device__ float g_ffg [NCAT * FF];
__device__ float g_ffu [NCAT * FF];
__device__ float g_cos [NPOS * 32];
__device__ float g_sin [NPOS * 32];

// --------------------------- rope tables (fp64 like ref) -------------------
__global__ void rope_table_kernel() {
    int idx = blockIdx.x * blockDim.x + threadIdx.x;
    if (idx >= NPOS * 32) return;
    int pos = idx >> 5, j = idx & 31;
    double inv = pow(10000.0, -((double)(2 * j)) / 64.0);
    double ang = (double)pos * inv;
    g_cos[idx] = (float)cos(ang);
    g_sin[idx] = (float)sin(ang);
}

// ------------------------------- init cat ----------------------------------
__global__ void init_kernel(const int* __restrict__ ids,
                            const float* __restrict__ embed,
                            const float* __restrict__ beacon,
                            const float* __restrict__ forget) {
    int idx = blockIdx.x * blockDim.x + threadIdx.x;
    if (idx >= NCAT * DD) return;
    int r = idx >> 10, c = idx & 1023;
    float v;
    if (r < SS)             v = embed[(size_t)ids[r] * DD + c];
    else if (r < SS + MM)   v = beacon[(r - SS) * DD + c];
    else                    v = forget[(r - SS - MM) * DD + c];
    g_cat[idx] = v;
}

// ------------------------------ record/output ------------------------------
// out[l] = memory[l]*sigmoid(fgt) + bcn*(1-sigmoid(fgt)), states at layer entry
__global__ void record_kernel(const float* __restrict__ mem_l,
                              float* __restrict__ out_l) {
    int idx = blockIdx.x * blockDim.x + threadIdx.x;
    if (idx >= MM * DD) return;
    float b = g_cat[SS * DD + idx];          // beacon rows 1024..1151
    float f = g_cat[(SS + MM) * DD + idx];   // forget rows 1152..1279
    float g = 1.f / (1.f + expf(-f));
    out_l[idx] = mem_l[idx] * g + b * (1.f - g);
}

// --------------------------------- RMSNorm ---------------------------------
__global__ __launch_bounds__(256) void rms_kernel(const float* __restrict__ in,
                                                  const float* __restrict__ w,
                                                  float* __restrict__ out) {
    int r = blockIdx.x;
    const float* row = in + (size_t)r * DD;
    __shared__ float red[256];
    float s = 0.f;
    for (int c = threadIdx.x; c < DD; c += 256) { float v = row[c]; s += v * v; }
    red[threadIdx.x] = s; __syncthreads();
    for (int t = 128; t > 0; t >>= 1) {
        if (threadIdx.x < t) red[threadIdx.x] += red[threadIdx.x + t];
        __syncthreads();
    }
    float inv = rsqrtf(red[0] * (1.f / DD) + 1e-5f);
    for (int c = threadIdx.x; c < DD; c += 256)
        out[(size_t)r * DD + c] = row[c] * w[c] * inv;
}

// ----------------------------------- RoPE ----------------------------------
// mode 0 = Q buffer (pos: r<1152 ? r+128 : r), mode 1 = K buffer (r<1280 ? r : r-128)
__global__ void rope_kernel(float* __restrict__ buf, int nrows, int mode) {
    int idx = blockIdx.x * blockDim.x + threadIdx.x;
    if (idx >= nrows * HH * 32) return;
    int j = idx & 31, h = (idx >> 5) & 15, r = idx >> 9;
    int pos = (mode == 0) ? ((r < 1152) ? r + 128 : r)
                          : ((r < 1280) ? r : r - 128);
    float c = g_cos[pos * 32 + j];
    float s = g_sin[pos * 32 + j];
    float* p = buf + (size_t)r * DD + h * HDIM + j;
    float x0 = p[0], x1 = p[32];
    p[0]  = x0 * c - x1 * s;
    p[32] = x1 * c + x0 * s;
}

// ----------------------------------- SGEMM ---------------------------------
// C(M,N) = A(M,K) @ B(K,N), optional accumulate. BM=128 BN=64 BK=8, 256 thr,
// thread tile 8x4. Requires M%128==0, N%64==0, K%8==0 (true for all calls).
template <bool ACC>
__global__ __launch_bounds__(256) void sgemm_kernel(const float* __restrict__ A,
                                                    const float* __restrict__ B,
                                                    float* __restrict__ C,
                                                    int N, int K) {
    __shared__ float As[8][128];
    __shared__ float Bs[8][64];
    const int tid = threadIdx.x;
    const int bm = blockIdx.y * 128;
    const int bn = blockIdx.x * 64;
    const int tx = tid & 15;         // 16 col-groups * 4
    const int ty = tid >> 4;         // 16 row-groups * 8
    const int a_row = tid >> 1;
    const int a_col = (tid & 1) * 4;
    const int b_row = tid >> 5;
    const int b_col = (tid & 31) * 2;

    float acc[8][4];
#pragma unroll
    for (int i = 0; i < 8; i++)
#pragma unroll
        for (int j = 0; j < 4; j++) acc[i][j] = 0.f;

    const float* Aptr = A + (size_t)(bm + a_row) * K + a_col;
    const float* Bptr = B + (size_t)b_row * N + bn + b_col;

    for (int k0 = 0; k0 < K; k0 += 8) {
        float4 av = *(const float4*)(Aptr + k0);
        As[a_col + 0][a_row] = av.x;
        As[a_col + 1][a_row] = av.y;
        As[a_col + 2][a_row] = av.z;
        As[a_col + 3][a_row] = av.w;
        float2 bv = *(const float2*)(Bptr + (size_t)k0 * N);
        Bs[b_row][b_col]     = bv.x;
        Bs[b_row][b_col + 1] = bv.y;
        __syncthreads();
#pragma unroll
        for (int kk = 0; kk < 8; kk++) {
            float ra[8], rb[4];
#pragma unroll
            for (int i = 0; i < 8; i++) ra[i] = As[kk][ty * 8 + i];
#pragma unroll
            for (int j = 0; j < 4; j++) rb[j] = Bs[kk][tx * 4 + j];
#pragma unroll
            for (int i = 0; i < 8; i++)
#pragma unroll
                for (int j = 0; j < 4; j++) acc[i][j] += ra[i] * rb[j];
        }
        __syncthreads();
    }
#pragma unroll
    for (int i = 0; i < 8; i++) {
        float* crow = C + (size_t)(bm + ty * 8 + i) * N + bn + tx * 4;
#pragma unroll
        for (int j = 0; j < 4; j++) {
            if (ACC) crow[j] += acc[i][j];
            else     crow[j]  = acc[i][j];
        }
    }
}

// --------------------------------- attention -------------------------------
// One block per (query row r, head h). Masks collapse to contiguous prefixes:
//   hidden r<1024 : keys [0, r+128],          rows identity
//   beacon        : keys [0, r+128],          rows identity
//   forget r>=1152: keys [0, r] (logical),    rows j<1152 ? j : j+128
__global__ __launch_bounds__(256) void attn_kernel(const float* __restrict__ Q,
                                                   const float* __restrict__ K,
                                                   const float* __restrict__ V,
                                                   float* __restrict__ O) {
    const int r = blockIdx.x;
    const int h = blockIdx.y;
    const int tid = threadIdx.x;
    const bool fg = (r >= SS + MM);
    const int nvis = fg ? (r + 1) : (r + 129);

    __shared__ float qs[64];
    __shared__ float sc[1280];
    __shared__ float red[256];
    __shared__ float part[4][64];

    if (tid < 64) qs[tid] = Q[(size_t)r * DD + h * HDIM + tid];
    __syncthreads();

    const float4* q4 = (const float4*)qs;
    float lmax = -3.402823466e38f;
    for (int k = tid; k < nvis; k += 256) {
        int row = (fg && k >= 1152) ? k + 128 : k;
        const float4* kp4 = (const float4*)(K + (size_t)row * DD + h * HDIM);
        float s = 0.f;
#pragma unroll
        for (int d4 = 0; d4 < 16; d4++) {
            float4 kv = kp4[d4], qv = q4[d4];
            s += kv.x * qv.x + kv.y * qv.y + kv.z * qv.z + kv.w * qv.w;
        }
        s *= 0.125f;
        sc[k] = s;
        lmax = fmaxf(lmax, s);
    }
    red[tid] = lmax; __syncthreads();
    for (int t = 128; t > 0; t >>= 1) {
        if (tid < t) red[tid] = fmaxf(red[tid], red[tid + t]);
        __syncthreads();
    }
    const float mx = red[0];
    __syncthreads();

    float lsum = 0.f;
    for (int k = tid; k < nvis; k += 256) {
        float e = expf(sc[k] - mx);
        sc[k] = e;
        lsum += e;
    }
    red[tid] = lsum; __syncthreads();
    for (int t = 128; t > 0; t >>= 1) {
        if (tid < t) red[tid] += red[tid + t];
        __syncthreads();
    }
    const float inv = 1.f / red[0];

    const int pp = tid >> 6, d = tid & 63;
    float acc = 0.f;
    for (int k = pp; k < nvis; k += 4) {
        int row = (fg && k >= 1152) ? k + 128 : k;
        acc += sc[k] * V[(size_t)row * DD + h * HDIM + d];
    }
    part[pp][d] = acc;
    __syncthreads();
    if (tid < 64)
        O[(size_t)r * DD + h * HDIM + tid] =
            (part[0][tid] + part[1][tid] + part[2][tid] + part[3][tid]) * inv;
}

// ------------------------------ silu(g) * u --------------------------------
__global__ void silu_mul_kernel(float* __restrict__ gbuf,
                                const float* __restrict__ ubuf) {
    int idx = blockIdx.x * blockDim.x + threadIdx.x;
    if (idx >= NCAT * FF) return;
    float g = gbuf[idx];
    gbuf[idx] = g / (1.f + expf(-g)) * ubuf[idx];
}

// --------------------------------- host ------------------------------------
static void gemm(const float* A, const float* B, float* C, int Mr, int N, int K,
                 bool acc) {
    dim3 grid(N / 64, Mr / 128);
    if (acc) sgemm_kernel<true ><<<grid, 256>>>(A, B, C, N, K);
    else     sgemm_kernel<false><<<grid, 256>>>(A, B, C, N, K);
}

extern "C" void kernel_launch(void* const* d_in, const int* in_sizes, int n_in,
                              void* d_out, int out_size) {
    (void)in_sizes; (void)n_in; (void)out_size;
    const int*   ids    = (const int*)  d_in[0];
    const float* memory = (const float*)d_in[1];
    const float* beacon = (const float*)d_in[2];
    const float* forget = (const float*)d_in[3];
    const float* embed  = (const float*)d_in[4];
    const float* ln1    = (const float*)d_in[5];
    const float* ln2    = (const float*)d_in[6];
    const float* Wq     = (const float*)d_in[7];
    const float* Wk     = (const float*)d_in[8];
    const float* Wv     = (const float*)d_in[9];
    const float* Wo     = (const float*)d_in[10];
    const float* mWk    = (const float*)d_in[11];
    const float* mWv    = (const float*)d_in[12];
    const float* bWq    = (const float*)d_in[13];
    const float* bWk    = (const float*)d_in[14];
    const float* bWv    = (const float*)d_in[15];
    const float* fWq    = (const float*)d_in[16];
    const float* fWk    = (const float*)d_in[17];
    const float* fWv    = (const float*)d_in[18];
    const float* Wg     = (const float*)d_in[19];
    const float* Wu     = (const float*)d_in[20];
    const float* Wd     = (const float*)d_in[21];
    float* out = (float*)d_out;

    float *cat, *x, *q, *k, *v, *attn, *ffg, *ffu;
    cudaGetSymbolAddress((void**)&cat,  g_cat);
    cudaGetSymbolAddress((void**)&x,    g_x);
    cudaGetSymbolAddress((void**)&q,    g_q);
    cudaGetSymbolAddress((void**)&k,    g_k);
    cudaGetSymbolAddress((void**)&v,    g_v);
    cudaGetSymbolAddress((void**)&attn, g_attn);
    cudaGetSymbolAddress((void**)&ffg,  g_ffg);
    cudaGetSymbolAddress((void**)&ffu,  g_ffu);

    rope_table_kernel<<<(NPOS * 32 + 255) / 256, 256>>>();
    init_kernel<<<(NCAT * DD + 255) / 256, 256>>>(ids, embed, beacon, forget);

    const size_t WSZ = (size_t)DD * DD;
    const size_t FSZ = (size_t)DD * FF;

    for (int l = 0; l < LL; l++) {
        const float* mem_l = memory + (size_t)l * MM * DD;
        record_kernel<<<(MM * DD + 255) / 256, 256>>>(mem_l, out + (size_t)l * MM * DD);
        if (l == LL - 1) break;  // layer 7's compute is never consumed

        const float* wq  = Wq  + (size_t)l * WSZ;
        const float* wk  = Wk  + (size_t)l * WSZ;
        const float* wv  = Wv  + (size_t)l * WSZ;
        const float* wo  = Wo  + (size_t)l * WSZ;
        const float* mwk = mWk + (size_t)l * WSZ;
        const float* mwv = mWv + (size_t)l * WSZ;
        const float* bwq = bWq + (size_t)l * WSZ;
        const float* bwk = bWk + (size_t)l * WSZ;
        const float* bwv = bWv + (size_t)l * WSZ;
        const float* fwq = fWq + (size_t)l * WSZ;
        const float* fwk = fWk + (size_t)l * WSZ;
        const float* fwv = fWv + (size_t)l * WSZ;
        const float* wg  = Wg  + (size_t)l * FSZ;
        const float* wu  = Wu  + (size_t)l * FSZ;
        const float* wd  = Wd  + (size_t)l * FSZ;

        // x = RMSNorm(cat, ln1)
        rms_kernel<<<NCAT, 256>>>(cat, ln1 + (size_t)l * DD, x);

        // projections (K/V buffer rows: [0,128) mem, [128,1152) hid,
        // [1152,1280) beacon-k, [1280,1408) forget-k)
        gemm(x,                 wq,  q,                 SS, DD, DD, false);
        gemm(x,                 wk,  k + (size_t)MM*DD, SS, DD, DD, false);
        gemm(x,                 wv,  v + (size_t)MM*DD, SS, DD, DD, false);
        gemm(mem_l,             mwk, k,                 MM, DD, DD, false);
        gemm(mem_l,             mwv, v,                 MM, DD, DD, false);
        gemm(x + (size_t)SS*DD,          bwq, q + (size_t)SS*DD,          MM, DD, DD, false);
        gemm(x + (size_t)SS*DD,          bwk, k + (size_t)(MM+SS)*DD,     MM, DD, DD, false);
        gemm(x + (size_t)SS*DD,          bwv, v + (size_t)(MM+SS)*DD,     MM, DD, DD, false);
        gemm(x + (size_t)(SS+MM)*DD,     fwq, q + (size_t)(SS+MM)*DD,     MM, DD, DD, false);
        gemm(x + (size_t)(SS+MM)*DD,     fwk, k + (size_t)(MM+SS+MM)*DD,  MM, DD, DD, false);
        gemm(x + (size_t)(SS+MM)*DD,     fwv, v + (size_t)(MM+SS+MM)*DD,  MM, DD, DD, false);

        rope_kernel<<<(NCAT * HH * 32 + 255) / 256, 256>>>(q, NCAT, 0);
        rope_kernel<<<(NKR  * HH * 32 + 255) / 256, 256>>>(k, NKR,  1);

        attn_kernel<<<dim3(NCAT, HH), 256>>>(q, k, v, attn);

        // cat += attn_all @ Wo   (hidden + beacon + forget share Wo)
        gemm(attn, wo, cat, NCAT, DD, DD, true);

        // MLP: cat += (silu(y@Wg) * (y@Wu)) @ Wd
        rms_kernel<<<NCAT, 256>>>(cat, ln2 + (size_t)l * DD, x);
        gemm(x, wg, ffg, NCAT, FF, DD, false);
        gemm(x, wu, ffu, NCAT, FF, DD, false);
        silu_mul_kernel<<<(NCAT * FF + 255) / 256, 256>>>(ffg, ffu);
        gemm(ffg, wd, cat, NCAT, DD, FF, true);
    }
}

// round 4
// speedup vs baseline: 4.7149x; 4.7149x over previous
#include <cuda_runtime.h>
#include <math.h>
#include <stdint.h>

// ---------------------------------------------------------------------------
// Encoder_51582557225690 : 8-layer beacon/forget memory transformer.
// R3 (= R2 resubmit after infra failure): all GEMMs + attention on tensor
// cores via mma.sync tf32 (fp32 accum).
// L=8 D=1024 H=16 HD=64 S=1024 M=128 F=2048 B=1
// ---------------------------------------------------------------------------

#define DD    1024
#define HH    16
#define HDIM  64
#define SS    1024
#define MM    128
#define LL    8
#define FF    2048
#define NCAT  1280   /* S + 2M residual rows                          */
#define NKR   1408   /* M(mem) + S(hid) + M(beacon k) + M(forget k)   */
#define NPOS  1280

// ------------------------- device scratch (no allocs) ----------------------
__device__ float g_cat [NCAT * DD];
__device__ float g_x   [NCAT * DD];
__device__ float g_q   [NCAT * DD];
__device__ float g_k   [NKR  * DD];
__device__ float g_v   [NKR  * DD];
__device__ float g_attn[NCAT * DD];
__device__ float g_ffg [NCAT * FF];
__device__ float g_ffu [NCAT * FF];
__device__ float g_scores[(size_t)HH * NCAT * NKR];   // 115 MB BSS scratch
__device__ float g_cos [NPOS * 32];
__device__ float g_sin [NPOS * 32];

// ------------------------------- tf32 helpers ------------------------------
__device__ __forceinline__ float tf32r(float x) {
    uint32_t u;
    asm("cvt.rna.tf32.f32 %0, %1;" : "=r"(u) : "f"(x));
    return __uint_as_float(u);
}
__device__ __forceinline__ void mma8(float* c, const uint32_t* a, const uint32_t* b) {
    asm volatile(
        "mma.sync.aligned.m16n8k8.row.col.f32.tf32.tf32.f32 "
        "{%0,%1,%2,%3},{%4,%5,%6,%7},{%8,%9},{%0,%1,%2,%3};"
        : "+f"(c[0]), "+f"(c[1]), "+f"(c[2]), "+f"(c[3])
        : "r"(a[0]), "r"(a[1]), "r"(a[2]), "r"(a[3]), "r"(b[0]), "r"(b[1]));
}

// --------------------------- rope tables (fp64 like ref) -------------------
__global__ void rope_table_kernel() {
    int idx = blockIdx.x * blockDim.x + threadIdx.x;
    if (idx >= NPOS * 32) return;
    int pos = idx >> 5, j = idx & 31;
    double inv = pow(10000.0, -((double)(2 * j)) / 64.0);
    double ang = (double)pos * inv;
    g_cos[idx] = (float)cos(ang);
    g_sin[idx] = (float)sin(ang);
}

// ------------------------------- init cat ----------------------------------
__global__ void init_kernel(const int* __restrict__ ids,
                            const float* __restrict__ embed,
                            const float* __restrict__ beacon,
                            const float* __restrict__ forget) {
    int idx = blockIdx.x * blockDim.x + threadIdx.x;
    if (idx >= NCAT * DD) return;
    int r = idx >> 10, c = idx & 1023;
    float v;
    if (r < SS)             v = embed[(size_t)ids[r] * DD + c];
    else if (r < SS + MM)   v = beacon[(r - SS) * DD + c];
    else                    v = forget[(r - SS - MM) * DD + c];
    g_cat[idx] = v;
}

// ------------------------------ record/output ------------------------------
__global__ void record_kernel(const float* __restrict__ mem_l,
                              float* __restrict__ out_l) {
    int idx = blockIdx.x * blockDim.x + threadIdx.x;
    if (idx >= MM * DD) return;
    float b = g_cat[SS * DD + idx];
    float f = g_cat[(SS + MM) * DD + idx];
    float g = 1.f / (1.f + expf(-f));
    out_l[idx] = mem_l[idx] * g + b * (1.f - g);
}

// --------------------------------- RMSNorm ---------------------------------
__global__ __launch_bounds__(256) void rms_kernel(const float* __restrict__ in,
                                                  const float* __restrict__ w,
                                                  float* __restrict__ out) {
    int r = blockIdx.x;
    const float* row = in + (size_t)r * DD;
    __shared__ float red[256];
    float s = 0.f;
    for (int c = threadIdx.x; c < DD; c += 256) { float v = row[c]; s += v * v; }
    red[threadIdx.x] = s; __syncthreads();
    for (int t = 128; t > 0; t >>= 1) {
        if (threadIdx.x < t) red[threadIdx.x] += red[threadIdx.x + t];
        __syncthreads();
    }
    float inv = rsqrtf(red[0] * (1.f / DD) + 1e-5f);
    for (int c = threadIdx.x; c < DD; c += 256)
        out[(size_t)r * DD + c] = row[c] * w[c] * inv;
}

// ----------------------------------- RoPE ----------------------------------
__global__ void rope_kernel(float* __restrict__ buf, int nrows, int mode) {
    int idx = blockIdx.x * blockDim.x + threadIdx.x;
    if (idx >= nrows * HH * 32) return;
    int j = idx & 31, h = (idx >> 5) & 15, r = idx >> 9;
    int pos = (mode == 0) ? ((r < 1152) ? r + 128 : r)
                          : ((r < 1280) ? r : r - 128);
    float c = g_cos[pos * 32 + j];
    float s = g_sin[pos * 32 + j];
    float* p = buf + (size_t)r * DD + h * HDIM + j;
    float x0 = p[0], x1 = p[32];
    p[0]  = x0 * c - x1 * s;
    p[32] = x1 * c + x0 * s;
}

// ------------------------ batched tf32 NN GEMM -----------------------------
// C(M,N) = A(M,K) @ B(K,N), row-major, pointer table batched over blockIdx.z.
struct GPtrs  { const float* A; const float* B; float* C; };
struct GBatch { GPtrs p[16]; };

template <int BM, int BN, int WM, int WN, bool ACC>
__global__ __launch_bounds__(256) void mma_gemm_nn(GBatch batch, int K,
                                                   int lda, int ldb, int ldc) {
    constexpr int BK = 16;
    constexpr int WARPS_N = BN / WN;
    constexpr int MT = WM / 16, NT = WN / 8;
    constexpr int ASTR = BK + 4;   // 20: conflict-free a-frag reads
    constexpr int BSTR = BN + 8;   // +8: conflict-free b-frag reads
    __shared__ float As[BM][ASTR];
    __shared__ float Bs[BK][BSTR];

    const GPtrs pr = batch.p[blockIdx.z];
    const float* A = pr.A;
    const float* B = pr.B;
    float* C = pr.C;
    const int bm = blockIdx.y * BM, bn = blockIdx.x * BN;
    const int tid = threadIdx.x, warp = tid >> 5, lane = tid & 31;
    const int wm = (warp / WARPS_N) * WM;
    const int wn = (warp % WARPS_N) * WN;
    const int lr = lane >> 2, lc = lane & 3;

    float acc[MT][NT][4];
#pragma unroll
    for (int i = 0; i < MT; i++)
#pragma unroll
        for (int j = 0; j < NT; j++)
#pragma unroll
            for (int e = 0; e < 4; e++) acc[i][j][e] = 0.f;

    constexpr int AITER = (BM * BK) / (4 * 256);
    constexpr int BITER = (BK * BN) / (4 * 256);
    constexpr int BC4   = BN / 4;

    for (int k0 = 0; k0 < K; k0 += BK) {
        __syncthreads();
#pragma unroll
        for (int it = 0; it < AITER; it++) {
            int i = tid + it * 256;
            int row = i >> 2, c4 = (i & 3) * 4;
            float4 v = *(const float4*)(A + (size_t)(bm + row) * lda + k0 + c4);
            float* d = &As[row][c4];
            d[0] = tf32r(v.x); d[1] = tf32r(v.y); d[2] = tf32r(v.z); d[3] = tf32r(v.w);
        }
#pragma unroll
        for (int it = 0; it < BITER; it++) {
            int i = tid + it * 256;
            int row = i / BC4, c4 = (i % BC4) * 4;
            float4 v = *(const float4*)(B + (size_t)(k0 + row) * ldb + bn + c4);
            float* d = &Bs[row][c4];
            d[0] = tf32r(v.x); d[1] = tf32r(v.y); d[2] = tf32r(v.z); d[3] = tf32r(v.w);
        }
        __syncthreads();
#pragma unroll
        for (int kk = 0; kk < BK; kk += 8) {
            uint32_t af[MT][4], bf[NT][2];
#pragma unroll
            for (int i = 0; i < MT; i++) {
                int r = wm + i * 16 + lr;
                af[i][0] = __float_as_uint(As[r    ][kk + lc    ]);
                af[i][1] = __float_as_uint(As[r + 8][kk + lc    ]);
                af[i][2] = __float_as_uint(As[r    ][kk + lc + 4]);
                af[i][3] = __float_as_uint(As[r + 8][kk + lc + 4]);
            }
#pragma unroll
            for (int j = 0; j < NT; j++) {
                int c = wn + j * 8 + lr;
                bf[j][0] = __float_as_uint(Bs[kk + lc    ][c]);
                bf[j][1] = __float_as_uint(Bs[kk + lc + 4][c]);
            }
#pragma unroll
            for (int i = 0; i < MT; i++)
#pragma unroll
                for (int j = 0; j < NT; j++) mma8(acc[i][j], af[i], bf[j]);
        }
    }

#pragma unroll
    for (int i = 0; i < MT; i++)
#pragma unroll
        for (int j = 0; j < NT; j++) {
            int r = bm + wm + i * 16 + lr;
            int c = bn + wn + j * 8 + lc * 2;
            float* p0 = C + (size_t)r * ldc + c;
            float* p1 = C + (size_t)(r + 8) * ldc + c;
            if (ACC) {
                p0[0] += acc[i][j][0]; p0[1] += acc[i][j][1];
                p1[0] += acc[i][j][2]; p1[1] += acc[i][j][3];
            } else {
                p0[0] = acc[i][j][0]; p0[1] = acc[i][j][1];
                p1[0] = acc[i][j][2]; p1[1] = acc[i][j][3];
            }
        }
}

// -------------------------- QK^T (NT gemm) + mask --------------------------
// S[h][r][j] = (Q_h[r] . K_h[j]) / 8, masked -> -1e30. Grid (11, 10, 16).
__device__ __forceinline__ bool vis_mask(int r, int j) {
    return (r < 1152) ? (j <= r + 128)
                      : (j < 1152 || (j >= 1280 && j - 128 <= r));
}

__global__ __launch_bounds__(256) void qk_kernel(const float* __restrict__ Q,
                                                 const float* __restrict__ Kb,
                                                 float* __restrict__ S) {
    constexpr int BK = 32, STR = BK + 4;   // 36: conflict-free frag reads
    __shared__ float Qs[128][STR];
    __shared__ float Ks[128][STR];

    const int h = blockIdx.z;
    const int bm = blockIdx.y * 128;   // query rows
    const int bn = blockIdx.x * 128;   // key rows
    const float* Qh = Q  + h * HDIM;
    const float* Kh = Kb + h * HDIM;
    const int tid = threadIdx.x, warp = tid >> 5, lane = tid & 31;
    const int wm = (warp >> 2) * 64;       // 2 warps in M
    const int wn = (warp & 3) * 32;        // 4 warps in N
    const int lr = lane >> 2, lc = lane & 3;

    float acc[4][4][4];
#pragma unroll
    for (int i = 0; i < 4; i++)
#pragma unroll
        for (int j = 0; j < 4; j++)
#pragma unroll
            for (int e = 0; e < 4; e++) acc[i][j][e] = 0.f;

    for (int k0 = 0; k0 < HDIM; k0 += BK) {
        __syncthreads();
#pragma unroll
        for (int it = 0; it < 4; it++) {
            int f = tid + it * 256;
            int row = f >> 3, c4 = (f & 7) * 4;
            float4 qv = *(const float4*)(Qh + (size_t)(bm + row) * DD + k0 + c4);
            float* dq = &Qs[row][c4];
            dq[0] = tf32r(qv.x); dq[1] = tf32r(qv.y); dq[2] = tf32r(qv.z); dq[3] = tf32r(qv.w);
            float4 kv = *(const float4*)(Kh + (size_t)(bn + row) * DD + k0 + c4);
            float* dk = &Ks[row][c4];
            dk[0] = tf32r(kv.x); dk[1] = tf32r(kv.y); dk[2] = tf32r(kv.z); dk[3] = tf32r(kv.w);
        }
        __syncthreads();
#pragma unroll
        for (int kk = 0; kk < BK; kk += 8) {
            uint32_t af[4][4], bf[4][2];
#pragma unroll
            for (int i = 0; i < 4; i++) {
                int r = wm + i * 16 + lr;
                af[i][0] = __float_as_uint(Qs[r    ][kk + lc    ]);
                af[i][1] = __float_as_uint(Qs[r + 8][kk + lc    ]);
                af[i][2] = __float_as_uint(Qs[r    ][kk + lc + 4]);
                af[i][3] = __float_as_uint(Qs[r + 8][kk + lc + 4]);
            }
#pragma unroll
            for (int j = 0; j < 4; j++) {
                int n = wn + j * 8 + lr;
                bf[j][0] = __float_as_uint(Ks[n][kk + lc    ]);
                bf[j][1] = __float_as_uint(Ks[n][kk + lc + 4]);
            }
#pragma unroll
            for (int i = 0; i < 4; i++)
#pragma unroll
                for (int j = 0; j < 4; j++) mma8(acc[i][j], af[i], bf[j]);
        }
    }

    float* Sh = S + (size_t)h * NCAT * NKR;
#pragma unroll
    for (int i = 0; i < 4; i++)
#pragma unroll
        for (int j = 0; j < 4; j++) {
            int r = bm + wm + i * 16 + lr;
            int c = bn + wn + j * 8 + lc * 2;
            float* p0 = Sh + (size_t)r * NKR + c;
            float* p1 = Sh + (size_t)(r + 8) * NKR + c;
            p0[0] = vis_mask(r,     c    ) ? acc[i][j][0] * 0.125f : -1e30f;
            p0[1] = vis_mask(r,     c + 1) ? acc[i][j][1] * 0.125f : -1e30f;
            p1[0] = vis_mask(r + 8, c    ) ? acc[i][j][2] * 0.125f : -1e30f;
            p1[1] = vis_mask(r + 8, c + 1) ? acc[i][j][3] * 0.125f : -1e30f;
        }
}

// --------------------------------- softmax ---------------------------------
__global__ __launch_bounds__(128) void softmax_kernel(float* __restrict__ S) {
    float* row = S + ((size_t)blockIdx.y * NCAT + blockIdx.x) * NKR;
    __shared__ float red[128];
    const int tid = threadIdx.x;
    float m = -1e30f;
    for (int j = tid; j < NKR; j += 128) m = fmaxf(m, row[j]);
    red[tid] = m; __syncthreads();
    for (int t = 64; t > 0; t >>= 1) {
        if (tid < t) red[tid] = fmaxf(red[tid], red[tid + t]);
        __syncthreads();
    }
    const float mx = red[0]; __syncthreads();
    float s = 0.f;
    for (int j = tid; j < NKR; j += 128) {
        float e = expf(row[j] - mx);
        row[j] = e;
        s += e;
    }
    red[tid] = s; __syncthreads();
    for (int t = 64; t > 0; t >>= 1) {
        if (tid < t) red[tid] += red[tid + t];
        __syncthreads();
    }
    const float inv = 1.f / red[0];
    for (int j = tid; j < NKR; j += 128) row[j] *= inv;
}

// ------------------------------ silu(g) * u --------------------------------
__global__ void silu_mul_kernel(float* __restrict__ gbuf,
                                const float* __restrict__ ubuf) {
    int idx = blockIdx.x * blockDim.x + threadIdx.x;
    if (idx >= NCAT * FF) return;
    float g = gbuf[idx];
    gbuf[idx] = g / (1.f + expf(-g)) * ubuf[idx];
}

// --------------------------------- host ------------------------------------
extern "C" void kernel_launch(void* const* d_in, const int* in_sizes, int n_in,
                              void* d_out, int out_size) {
    (void)in_sizes; (void)n_in; (void)out_size;
    const int*   ids    = (const int*)  d_in[0];
    const float* memory = (const float*)d_in[1];
    const float* beacon = (const float*)d_in[2];
    const float* forget = (const float*)d_in[3];
    const float* embed  = (const float*)d_in[4];
    const float* ln1    = (const float*)d_in[5];
    const float* ln2    = (const float*)d_in[6];
    const float* Wq     = (const float*)d_in[7];
    const float* Wk     = (const float*)d_in[8];
    const float* Wv     = (const float*)d_in[9];
    const float* Wo     = (const float*)d_in[10];
    const float* mWk    = (const float*)d_in[11];
    const float* mWv    = (const float*)d_in[12];
    const float* bWq    = (const float*)d_in[13];
    const float* bWk    = (const float*)d_in[14];
    const float* bWv    = (const float*)d_in[15];
    const float* fWq    = (const float*)d_in[16];
    const float* fWk    = (const float*)d_in[17];
    const float* fWv    = (const float*)d_in[18];
    const float* Wg     = (const float*)d_in[19];
    const float* Wu     = (const float*)d_in[20];
    const float* Wd     = (const float*)d_in[21];
    float* out = (float*)d_out;

    float *cat, *x, *q, *k, *v, *attn, *ffg, *ffu, *scores;
    cudaGetSymbolAddress((void**)&cat,    g_cat);
    cudaGetSymbolAddress((void**)&x,      g_x);
    cudaGetSymbolAddress((void**)&q,      g_q);
    cudaGetSymbolAddress((void**)&k,      g_k);
    cudaGetSymbolAddress((void**)&v,      g_v);
    cudaGetSymbolAddress((void**)&attn,   g_attn);
    cudaGetSymbolAddress((void**)&ffg,    g_ffg);
    cudaGetSymbolAddress((void**)&ffu,    g_ffu);
    cudaGetSymbolAddress((void**)&scores, g_scores);

    rope_table_kernel<<<(NPOS * 32 + 255) / 256, 256>>>();
    init_kernel<<<(NCAT * DD + 255) / 256, 256>>>(ids, embed, beacon, forget);

    const size_t WSZ = (size_t)DD * DD;
    const size_t FSZ = (size_t)DD * FF;

    for (int l = 0; l < LL; l++) {
        const float* mem_l = memory + (size_t)l * MM * DD;
        record_kernel<<<(MM * DD + 255) / 256, 256>>>(mem_l, out + (size_t)l * MM * DD);
        if (l == LL - 1) break;   // layer 7's compute is never consumed

        const float* wq  = Wq  + (size_t)l * WSZ;
        const float* wk  = Wk  + (size_t)l * WSZ;
        const float* wv  = Wv  + (size_t)l * WSZ;
        const float* wo  = Wo  + (size_t)l * WSZ;
        const float* mwk = mWk + (size_t)l * WSZ;
        const float* mwv = mWv + (size_t)l * WSZ;
        const float* bwq = bWq + (size_t)l * WSZ;
        const float* bwk = bWk + (size_t)l * WSZ;
        const float* bwv = bWv + (size_t)l * WSZ;
        const float* fwq = fWq + (size_t)l * WSZ;
        const float* fwk = fWk + (size_t)l * WSZ;
        const float* fwv = fWv + (size_t)l * WSZ;
        const float* wg  = Wg  + (size_t)l * FSZ;
        const float* wu  = Wu  + (size_t)l * FSZ;
        const float* wd  = Wd  + (size_t)l * FSZ;

        rms_kernel<<<NCAT, 256>>>(cat, ln1 + (size_t)l * DD, x);

        // big projections on hidden rows (M=1024, batched z=3)
        {
            GBatch bb{};
            bb.p[0] = { x, wq, q };
            bb.p[1] = { x, wk, k + (size_t)MM * DD };
            bb.p[2] = { x, wv, v + (size_t)MM * DD };
            mma_gemm_nn<128,128,64,32,false><<<dim3(8,8,3), 256>>>(bb, DD, DD, DD, DD);
        }
        // small projections (M=128, batched z=8)
        {
            GBatch sb{};
            sb.p[0] = { mem_l,                  mwk, k };
            sb.p[1] = { mem_l,                  mwv, v };
            sb.p[2] = { x + (size_t)SS*DD,      bwq, q + (size_t)SS*DD };
            sb.p[3] = { x + (size_t)SS*DD,      bwk, k + (size_t)(MM+SS)*DD };
            sb.p[4] = { x + (size_t)SS*DD,      bwv, v + (size_t)(MM+SS)*DD };
            sb.p[5] = { x + (size_t)(SS+MM)*DD, fwq, q + (size_t)(SS+MM)*DD };
            sb.p[6] = { x + (size_t)(SS+MM)*DD, fwk, k + (size_t)(MM+SS+MM)*DD };
            sb.p[7] = { x + (size_t)(SS+MM)*DD, fwv, v + (size_t)(MM+SS+MM)*DD };
            mma_gemm_nn<128,128,64,32,false><<<dim3(8,1,8), 256>>>(sb, DD, DD, DD, DD);
        }

        rope_kernel<<<(NCAT * HH * 32 + 255) / 256, 256>>>(q, NCAT, 0);
        rope_kernel<<<(NKR  * HH * 32 + 255) / 256, 256>>>(k, NKR,  1);

        // attention: S = QK^T (masked), softmax, O = P V
        qk_kernel<<<dim3(11, 10, 16), 256>>>(q, k, scores);
        softmax_kernel<<<dim3(NCAT, HH), 128>>>(scores);
        {
            GBatch av{};
            for (int h = 0; h < HH; h++)
                av.p[h] = { scores + (size_t)h * NCAT * NKR, v + h * HDIM, attn + h * HDIM };
            mma_gemm_nn<128,64,32,32,false><<<dim3(1,10,16), 256>>>(av, NKR, NKR, DD, DD);
        }
        // cat += attn @ Wo
        {
            GBatch ob{};
            ob.p[0] = { attn, wo, cat };
            mma_gemm_nn<128,128,64,32,true><<<dim3(8,10,1), 256>>>(ob, DD, DD, DD, DD);
        }

        // MLP
        rms_kernel<<<NCAT, 256>>>(cat, ln2 + (size_t)l * DD, x);
        {
            GBatch mb{};
            mb.p[0] = { x, wg, ffg };
            mb.p[1] = { x, wu, ffu };
            mma_gemm_nn<128,128,64,32,false><<<dim3(16,10,2), 256>>>(mb, DD, DD, FF, FF);
        }
        silu_mul_kernel<<<(NCAT * FF + 255) / 256, 256>>>(ffg, ffu);
        {
            GBatch db{};
            db.p[0] = { ffg, wd, cat };
            mma_gemm_nn<128,128,64,32,true><<<dim3(8,10,1), 256>>>(db, FF, FF, DD, DD);
        }
    }
}

// round 5
// speedup vs baseline: 5.2510x; 1.1137x over previous
#include <cuda_runtime.h>
#include <math.h>
#include <stdint.h>

// ---------------------------------------------------------------------------
// Encoder_51582557225690 : 8-layer beacon/forget memory transformer.
// R5: software-pipelined tf32 GEMM (double-buffered smem + reg prefetch,
// 1 sync/iter), BN=64 tiles for fill-bound GEMMs, 2-pass online softmax.
// L=8 D=1024 H=16 HD=64 S=1024 M=128 F=2048 B=1
// ---------------------------------------------------------------------------

#define DD    1024
#define HH    16
#define HDIM  64
#define SS    1024
#define MM    128
#define LL    8
#define FF    2048
#define NCAT  1280
#define NKR   1408
#define NPOS  1280

// ------------------------- device scratch (no allocs) ----------------------
__device__ float g_cat [NCAT * DD];
__device__ float g_x   [NCAT * DD];
__device__ float g_q   [NCAT * DD];
__device__ float g_k   [NKR  * DD];
__device__ float g_v   [NKR  * DD];
__device__ float g_attn[NCAT * DD];
__device__ float g_ffg [NCAT * FF];
__device__ float g_ffu [NCAT * FF];
__device__ float g_scores[(size_t)HH * NCAT * NKR];   // 115 MB BSS scratch
__device__ float g_cos [NPOS * 32];
__device__ float g_sin [NPOS * 32];

// ------------------------------- tf32 helpers ------------------------------
__device__ __forceinline__ float tf32r(float x) {
    uint32_t u;
    asm("cvt.rna.tf32.f32 %0, %1;" : "=r"(u) : "f"(x));
    return __uint_as_float(u);
}
__device__ __forceinline__ void mma8(float* c, const uint32_t* a, const uint32_t* b) {
    asm volatile(
        "mma.sync.aligned.m16n8k8.row.col.f32.tf32.tf32.f32 "
        "{%0,%1,%2,%3},{%4,%5,%6,%7},{%8,%9},{%0,%1,%2,%3};"
        : "+f"(c[0]), "+f"(c[1]), "+f"(c[2]), "+f"(c[3])
        : "r"(a[0]), "r"(a[1]), "r"(a[2]), "r"(a[3]), "r"(b[0]), "r"(b[1]));
}

// --------------------------- rope tables (fp64 like ref) -------------------
__global__ void rope_table_kernel() {
    int idx = blockIdx.x * blockDim.x + threadIdx.x;
    if (idx >= NPOS * 32) return;
    int pos = idx >> 5, j = idx & 31;
    double inv = pow(10000.0, -((double)(2 * j)) / 64.0);
    double ang = (double)pos * inv;
    g_cos[idx] = (float)cos(ang);
    g_sin[idx] = (float)sin(ang);
}

// ------------------------------- init cat ----------------------------------
__global__ void init_kernel(const int* __restrict__ ids,
                            const float* __restrict__ embed,
                            const float* __restrict__ beacon,
                            const float* __restrict__ forget) {
    int idx = blockIdx.x * blockDim.x + threadIdx.x;
    if (idx >= NCAT * DD) return;
    int r = idx >> 10, c = idx & 1023;
    float v;
    if (r < SS)             v = embed[(size_t)ids[r] * DD + c];
    else if (r < SS + MM)   v = beacon[(r - SS) * DD + c];
    else                    v = forget[(r - SS - MM) * DD + c];
    g_cat[idx] = v;
}

// ------------------------------ record/output ------------------------------
__global__ void record_kernel(const float* __restrict__ mem_l,
                              float* __restrict__ out_l) {
    int idx = blockIdx.x * blockDim.x + threadIdx.x;
    if (idx >= MM * DD) return;
    float b = g_cat[SS * DD + idx];
    float f = g_cat[(SS + MM) * DD + idx];
    float g = 1.f / (1.f + expf(-f));
    out_l[idx] = mem_l[idx] * g + b * (1.f - g);
}

// --------------------------------- RMSNorm ---------------------------------
// One block (128 thr) per row; float4 loads, shuffle+smem reduction.
__global__ __launch_bounds__(128) void rms_kernel(const float* __restrict__ in,
                                                  const float* __restrict__ w,
                                                  float* __restrict__ out) {
    const int r = blockIdx.x, tid = threadIdx.x;
    const float4* row4 = (const float4*)(in + (size_t)r * DD);
    float4 v0 = row4[tid], v1 = row4[tid + 128];
    float s = v0.x*v0.x + v0.y*v0.y + v0.z*v0.z + v0.w*v0.w
            + v1.x*v1.x + v1.y*v1.y + v1.z*v1.z + v1.w*v1.w;
#pragma unroll
    for (int o = 16; o > 0; o >>= 1) s += __shfl_down_sync(0xffffffffu, s, o);
    __shared__ float ws[4];
    if ((tid & 31) == 0) ws[tid >> 5] = s;
    __syncthreads();
    float tot = ws[0] + ws[1] + ws[2] + ws[3];
    float inv = rsqrtf(tot * (1.f / DD) + 1e-5f);
    const float4* w4 = (const float4*)w;
    float4* o4 = (float4*)(out + (size_t)r * DD);
    float4 a = w4[tid], b = w4[tid + 128];
    float4 r0 = make_float4(v0.x*a.x*inv, v0.y*a.y*inv, v0.z*a.z*inv, v0.w*a.w*inv);
    float4 r1 = make_float4(v1.x*b.x*inv, v1.y*b.y*inv, v1.z*b.z*inv, v1.w*b.w*inv);
    o4[tid] = r0; o4[tid + 128] = r1;
}

// ----------------------------------- RoPE ----------------------------------
__global__ void rope_kernel(float* __restrict__ buf, int nrows, int mode) {
    int idx = blockIdx.x * blockDim.x + threadIdx.x;
    if (idx >= nrows * HH * 32) return;
    int j = idx & 31, h = (idx >> 5) & 15, r = idx >> 9;
    int pos = (mode == 0) ? ((r < 1152) ? r + 128 : r)
                          : ((r < 1280) ? r : r - 128);
    float c = g_cos[pos * 32 + j];
    float s = g_sin[pos * 32 + j];
    float* p = buf + (size_t)r * DD + h * HDIM + j;
    float x0 = p[0], x1 = p[32];
    p[0]  = x0 * c - x1 * s;
    p[32] = x1 * c + x0 * s;
}

// ------------------- pipelined batched tf32 NN GEMM ------------------------
// C(M,N) = A(M,K) @ B(K,N), row-major, batched over blockIdx.z.
// Double-buffered smem + register prefetch; one __syncthreads per BK=16.
struct GPtrs  { const float* A; const float* B; float* C; };
struct GBatch { GPtrs p[16]; };

template <int BM, int BN, int WM, int WN, bool ACC>
__global__ __launch_bounds__(256) void mma_gemm_nn(GBatch batch, int K,
                                                   int lda, int ldb, int ldc) {
    constexpr int BK = 16;
    constexpr int WARPS_N = BN / WN;
    constexpr int MT = WM / 16, NT = WN / 8;
    constexpr int ASTR = BK + 4;
    constexpr int BSTR = BN + 8;
    constexpr int AITER = (BM * BK) / (4 * 256);
    constexpr int BITER = (BK * BN) / (4 * 256);
    constexpr int BNQ = BN / 4;
    constexpr int AROWSTEP = 64;            // 256 threads / 4 f4-chunks per row
    constexpr int BROWSTEP = 256 / BNQ;

    __shared__ float As[2][BM][ASTR];
    __shared__ float Bs[2][BK][BSTR];

    const GPtrs pr = batch.p[blockIdx.z];
    const float* __restrict__ A = pr.A;
    const float* __restrict__ B = pr.B;
    float* __restrict__ C = pr.C;
    const int bm = blockIdx.y * BM, bn = blockIdx.x * BN;
    const int tid = threadIdx.x, warp = tid >> 5, lane = tid & 31;
    const int wm = (warp / WARPS_N) * WM;
    const int wn = (warp % WARPS_N) * WN;
    const int lr = lane >> 2, lc = lane & 3;

    const int arow = tid >> 2, ac4 = (tid & 3) * 4;
    const int brow = tid / BNQ, bc4 = (tid % BNQ) * 4;

    float acc[MT][NT][4];
#pragma unroll
    for (int i = 0; i < MT; i++)
#pragma unroll
        for (int j = 0; j < NT; j++)
#pragma unroll
            for (int e = 0; e < 4; e++) acc[i][j][e] = 0.f;

    float4 ar[AITER], br[BITER];

    // prologue: tile 0
#pragma unroll
    for (int it = 0; it < AITER; it++)
        ar[it] = *(const float4*)(A + (size_t)(bm + arow + it * AROWSTEP) * lda + ac4);
#pragma unroll
    for (int it = 0; it < BITER; it++)
        br[it] = *(const float4*)(B + (size_t)(brow + it * BROWSTEP) * ldb + bn + bc4);
#pragma unroll
    for (int it = 0; it < AITER; it++) {
        float* d = &As[0][arow + it * AROWSTEP][ac4];
        d[0] = tf32r(ar[it].x); d[1] = tf32r(ar[it].y);
        d[2] = tf32r(ar[it].z); d[3] = tf32r(ar[it].w);
    }
#pragma unroll
    for (int it = 0; it < BITER; it++) {
        float* d = &Bs[0][brow + it * BROWSTEP][bc4];
        d[0] = tf32r(br[it].x); d[1] = tf32r(br[it].y);
        d[2] = tf32r(br[it].z); d[3] = tf32r(br[it].w);
    }
    __syncthreads();

    const int nIter = K / BK;
    for (int itn = 0; itn < nIter; itn++) {
        const int buf = itn & 1;
        const bool more = (itn + 1 < nIter);
        if (more) {
            const int k0 = (itn + 1) * BK;
#pragma unroll
            for (int it = 0; it < AITER; it++)
                ar[it] = *(const float4*)(A + (size_t)(bm + arow + it * AROWSTEP) * lda + k0 + ac4);
#pragma unroll
            for (int it = 0; it < BITER; it++)
                br[it] = *(const float4*)(B + (size_t)(k0 + brow + it * BROWSTEP) * ldb + bn + bc4);
        }
#pragma unroll
        for (int kk = 0; kk < BK; kk += 8) {
            uint32_t af[MT][4], bf[NT][2];
#pragma unroll
            for (int i = 0; i < MT; i++) {
                int r = wm + i * 16 + lr;
                af[i][0] = __float_as_uint(As[buf][r    ][kk + lc    ]);
                af[i][1] = __float_as_uint(As[buf][r + 8][kk + lc    ]);
                af[i][2] = __float_as_uint(As[buf][r    ][kk + lc + 4]);
                af[i][3] = __float_as_uint(As[buf][r + 8][kk + lc + 4]);
            }
#pragma unroll
            for (int j = 0; j < NT; j++) {
                int c = wn + j * 8 + lr;
                bf[j][0] = __float_as_uint(Bs[buf][kk + lc    ][c]);
                bf[j][1] = __float_as_uint(Bs[buf][kk + lc + 4][c]);
            }
#pragma unroll
            for (int i = 0; i < MT; i++)
#pragma unroll
                for (int j = 0; j < NT; j++) mma8(acc[i][j], af[i], bf[j]);
        }
        if (more) {
            const int nb = buf ^ 1;
#pragma unroll
            for (int it = 0; it < AITER; it++) {
                float* d = &As[nb][arow + it * AROWSTEP][ac4];
                d[0] = tf32r(ar[it].x); d[1] = tf32r(ar[it].y);
                d[2] = tf32r(ar[it].z); d[3] = tf32r(ar[it].w);
            }
#pragma unroll
            for (int it = 0; it < BITER; it++) {
                float* d = &Bs[nb][brow + it * BROWSTEP][bc4];
                d[0] = tf32r(br[it].x); d[1] = tf32r(br[it].y);
                d[2] = tf32r(br[it].z); d[3] = tf32r(br[it].w);
            }
            __syncthreads();
        }
    }

#pragma unroll
    for (int i = 0; i < MT; i++)
#pragma unroll
        for (int j = 0; j < NT; j++) {
            int r = bm + wm + i * 16 + lr;
            int c = bn + wn + j * 8 + lc * 2;
            float* p0 = C + (size_t)r * ldc + c;
            float* p1 = C + (size_t)(r + 8) * ldc + c;
            if (ACC) {
                p0[0] += acc[i][j][0]; p0[1] += acc[i][j][1];
                p1[0] += acc[i][j][2]; p1[1] += acc[i][j][3];
            } else {
                p0[0] = acc[i][j][0]; p0[1] = acc[i][j][1];
                p1[0] = acc[i][j][2]; p1[1] = acc[i][j][3];
            }
        }
}

// -------------------------- QK^T (NT gemm) + mask --------------------------
__device__ __forceinline__ bool vis_mask(int r, int j) {
    return (r < 1152) ? (j <= r + 128)
                      : (j < 1152 || (j >= 1280 && j - 128 <= r));
}

__global__ __launch_bounds__(256) void qk_kernel(const float* __restrict__ Q,
                                                 const float* __restrict__ Kb,
                                                 float* __restrict__ S) {
    constexpr int BK = 32, STR = BK + 4;
    __shared__ float Qs[128][STR];
    __shared__ float Ks[128][STR];

    const int h = blockIdx.z;
    const int bm = blockIdx.y * 128;
    const int bn = blockIdx.x * 128;
    const float* Qh = Q  + h * HDIM;
    const float* Kh = Kb + h * HDIM;
    const int tid = threadIdx.x, warp = tid >> 5, lane = tid & 31;
    const int wm = (warp >> 2) * 64;
    const int wn = (warp & 3) * 32;
    const int lr = lane >> 2, lc = lane & 3;

    float acc[4][4][4];
#pragma unroll
    for (int i = 0; i < 4; i++)
#pragma unroll
        for (int j = 0; j < 4; j++)
#pragma unroll
            for (int e = 0; e < 4; e++) acc[i][j][e] = 0.f;

    for (int k0 = 0; k0 < HDIM; k0 += BK) {
        __syncthreads();
#pragma unroll
        for (int it = 0; it < 4; it++) {
            int f = tid + it * 256;
            int row = f >> 3, c4 = (f & 7) * 4;
            float4 qv = *(const float4*)(Qh + (size_t)(bm + row) * DD + k0 + c4);
            float* dq = &Qs[row][c4];
            dq[0] = tf32r(qv.x); dq[1] = tf32r(qv.y); dq[2] = tf32r(qv.z); dq[3] = tf32r(qv.w);
            float4 kv = *(const float4*)(Kh + (size_t)(bn + row) * DD + k0 + c4);
            float* dk = &Ks[row][c4];
            dk[0] = tf32r(kv.x); dk[1] = tf32r(kv.y); dk[2] = tf32r(kv.z); dk[3] = tf32r(kv.w);
        }
        __syncthreads();
#pragma unroll
        for (int kk = 0; kk < BK; kk += 8) {
            uint32_t af[4][4], bf[4][2];
#pragma unroll
            for (int i = 0; i < 4; i++) {
                int r = wm + i * 16 + lr;
                af[i][0] = __float_as_uint(Qs[r    ][kk + lc    ]);
                af[i][1] = __float_as_uint(Qs[r + 8][kk + lc    ]);
                af[i][2] = __float_as_uint(Qs[r    ][kk + lc + 4]);
                af[i][3] = __float_as_uint(Qs[r + 8][kk + lc + 4]);
            }
#pragma unroll
            for (int j = 0; j < 4; j++) {
                int n = wn + j * 8 + lr;
                bf[j][0] = __float_as_uint(Ks[n][kk + lc    ]);
                bf[j][1] = __float_as_uint(Ks[n][kk + lc + 4]);
            }
#pragma unroll
            for (int i = 0; i < 4; i++)
#pragma unroll
                for (int j = 0; j < 4; j++) mma8(acc[i][j], af[i], bf[j]);
        }
    }

    float* Sh = S + (size_t)h * NCAT * NKR;
#pragma unroll
    for (int i = 0; i < 4; i++)
#pragma unroll
        for (int j = 0; j < 4; j++) {
            int r = bm + wm + i * 16 + lr;
            int c = bn + wn + j * 8 + lc * 2;
            float* p0 = Sh + (size_t)r * NKR + c;
            float* p1 = Sh + (size_t)(r + 8) * NKR + c;
            p0[0] = vis_mask(r,     c    ) ? acc[i][j][0] * 0.125f : -1e30f;
            p0[1] = vis_mask(r,     c + 1) ? acc[i][j][1] * 0.125f : -1e30f;
            p1[0] = vis_mask(r + 8, c    ) ? acc[i][j][2] * 0.125f : -1e30f;
            p1[1] = vis_mask(r + 8, c + 1) ? acc[i][j][3] * 0.125f : -1e30f;
        }
}

// ------------------------- softmax (2-pass online) -------------------------
__global__ __launch_bounds__(128) void softmax_kernel(float* __restrict__ S) {
    float* row = S + ((size_t)blockIdx.y * NCAT + blockIdx.x) * NKR;
    __shared__ float sm[128], ss[128];
    const int tid = threadIdx.x;

    float m = -3.402823466e38f, s = 0.f;
    for (int j = tid; j < NKR; j += 128) {
        float x = row[j];
        float mn = fmaxf(m, x);
        s = s * __expf(m - mn) + __expf(x - mn);
        m = mn;
    }
    sm[tid] = m; ss[tid] = s; __syncthreads();
    for (int t = 64; t > 0; t >>= 1) {
        if (tid < t) {
            float m2 = sm[tid + t], s2 = ss[tid + t];
            float mn = fmaxf(m, m2);
            s = s * __expf(m - mn) + s2 * __expf(m2 - mn);
            m = mn;
            sm[tid] = m; ss[tid] = s;
        }
        __syncthreads();
    }
    const float mx = sm[0];
    const float inv = 1.f / ss[0];
    for (int j = tid; j < NKR; j += 128)
        row[j] = __expf(row[j] - mx) * inv;
}

// ------------------------------ silu(g) * u --------------------------------
__global__ void silu_mul_kernel(float* __restrict__ gbuf,
                                const float* __restrict__ ubuf) {
    int idx = blockIdx.x * blockDim.x + threadIdx.x;
    if (idx >= NCAT * FF) return;
    float g = gbuf[idx];
    gbuf[idx] = g / (1.f + expf(-g)) * ubuf[idx];
}

// --------------------------------- host ------------------------------------
extern "C" void kernel_launch(void* const* d_in, const int* in_sizes, int n_in,
                              void* d_out, int out_size) {
    (void)in_sizes; (void)n_in; (void)out_size;
    const int*   ids    = (const int*)  d_in[0];
    const float* memory = (const float*)d_in[1];
    const float* beacon = (const float*)d_in[2];
    const float* forget = (const float*)d_in[3];
    const float* embed  = (const float*)d_in[4];
    const float* ln1    = (const float*)d_in[5];
    const float* ln2    = (const float*)d_in[6];
    const float* Wq     = (const float*)d_in[7];
    const float* Wk     = (const float*)d_in[8];
    const float* Wv     = (const float*)d_in[9];
    const float* Wo     = (const float*)d_in[10];
    const float* mWk    = (const float*)d_in[11];
    const float* mWv    = (const float*)d_in[12];
    const float* bWq    = (const float*)d_in[13];
    const float* bWk    = (const float*)d_in[14];
    const float* bWv    = (const float*)d_in[15];
    const float* fWq    = (const float*)d_in[16];
    const float* fWk    = (const float*)d_in[17];
    const float* fWv    = (const float*)d_in[18];
    const float* Wg     = (const float*)d_in[19];
    const float* Wu     = (const float*)d_in[20];
    const float* Wd     = (const float*)d_in[21];
    float* out = (float*)d_out;

    float *cat, *x, *q, *k, *v, *attn, *ffg, *ffu, *scores;
    cudaGetSymbolAddress((void**)&cat,    g_cat);
    cudaGetSymbolAddress((void**)&x,      g_x);
    cudaGetSymbolAddress((void**)&q,      g_q);
    cudaGetSymbolAddress((void**)&k,      g_k);
    cudaGetSymbolAddress((void**)&v,      g_v);
    cudaGetSymbolAddress((void**)&attn,   g_attn);
    cudaGetSymbolAddress((void**)&ffg,    g_ffg);
    cudaGetSymbolAddress((void**)&ffu,    g_ffu);
    cudaGetSymbolAddress((void**)&scores, g_scores);

    rope_table_kernel<<<(NPOS * 32 + 255) / 256, 256>>>();
    init_kernel<<<(NCAT * DD + 255) / 256, 256>>>(ids, embed, beacon, forget);

    const size_t WSZ = (size_t)DD * DD;
    const size_t FSZ = (size_t)DD * FF;

    for (int l = 0; l < LL; l++) {
        const float* mem_l = memory + (size_t)l * MM * DD;
        record_kernel<<<(MM * DD + 255) / 256, 256>>>(mem_l, out + (size_t)l * MM * DD);
        if (l == LL - 1) break;   // layer 7's compute is never consumed

        const float* wq  = Wq  + (size_t)l * WSZ;
        const float* wk  = Wk  + (size_t)l * WSZ;
        const float* wv  = Wv  + (size_t)l * WSZ;
        const float* wo  = Wo  + (size_t)l * WSZ;
        const float* mwk = mWk + (size_t)l * WSZ;
        const float* mwv = mWv + (size_t)l * WSZ;
        const float* bwq = bWq + (size_t)l * WSZ;
        const float* bwk = bWk + (size_t)l * WSZ;
        const float* bwv = bWv + (size_t)l * WSZ;
        const float* fwq = fWq + (size_t)l * WSZ;
        const float* fwk = fWk + (size_t)l * WSZ;
        const float* fwv = fWv + (size_t)l * WSZ;
        const float* wg  = Wg  + (size_t)l * FSZ;
        const float* wu  = Wu  + (size_t)l * FSZ;
        const float* wd  = Wd  + (size_t)l * FSZ;

        rms_kernel<<<NCAT, 128>>>(cat, ln1 + (size_t)l * DD, x);

        // big projections on hidden rows (M=1024, z=3)
        {
            GBatch bb{};
            bb.p[0] = { x, wq, q };
            bb.p[1] = { x, wk, k + (size_t)MM * DD };
            bb.p[2] = { x, wv, v + (size_t)MM * DD };
            mma_gemm_nn<128,128,64,32,false><<<dim3(8,8,3), 256>>>(bb, DD, DD, DD, DD);
        }
        // small projections (M=128, z=8), BN=64 for fill
        {
            GBatch sb{};
            sb.p[0] = { mem_l,                  mwk, k };
            sb.p[1] = { mem_l,                  mwv, v };
            sb.p[2] = { x + (size_t)SS*DD,      bwq, q + (size_t)SS*DD };
            sb.p[3] = { x + (size_t)SS*DD,      bwk, k + (size_t)(MM+SS)*DD };
            sb.p[4] = { x + (size_t)SS*DD,      bwv, v + (size_t)(MM+SS)*DD };
            sb.p[5] = { x + (size_t)(SS+MM)*DD, fwq, q + (size_t)(SS+MM)*DD };
            sb.p[6] = { x + (size_t)(SS+MM)*DD, fwk, k + (size_t)(MM+SS+MM)*DD };
            sb.p[7] = { x + (size_t)(SS+MM)*DD, fwv, v + (size_t)(MM+SS+MM)*DD };
            mma_gemm_nn<128,64,32,32,false><<<dim3(16,1,8), 256>>>(sb, DD, DD, DD, DD);
        }

        rope_kernel<<<(NCAT * HH * 32 + 255) / 256, 256>>>(q, NCAT, 0);
        rope_kernel<<<(NKR  * HH * 32 + 255) / 256, 256>>>(k, NKR,  1);

        // attention
        qk_kernel<<<dim3(11, 10, 16), 256>>>(q, k, scores);
        softmax_kernel<<<dim3(NCAT, HH), 128>>>(scores);
        {
            GBatch av{};
            for (int h = 0; h < HH; h++)
                av.p[h] = { scores + (size_t)h * NCAT * NKR, v + h * HDIM, attn + h * HDIM };
            mma_gemm_nn<128,64,32,32,false><<<dim3(1,10,16), 256>>>(av, NKR, NKR, DD, DD);
        }
        // cat += attn @ Wo  (BN=64 -> 160 blocks)
        {
            GBatch ob{};
            ob.p[0] = { attn, wo, cat };
            mma_gemm_nn<128,64,32,32,true><<<dim3(16,10,1), 256>>>(ob, DD, DD, DD, DD);
        }

        // MLP
        rms_kernel<<<NCAT, 128>>>(cat, ln2 + (size_t)l * DD, x);
        {
            GBatch mb{};
            mb.p[0] = { x, wg, ffg };
            mb.p[1] = { x, wu, ffu };
            mma_gemm_nn<128,128,64,32,false><<<dim3(16,10,2), 256>>>(mb, DD, DD, FF, FF);
        }
        silu_mul_kernel<<<(NCAT * FF + 255) / 256, 256>>>(ffg, ffu);
        // cat += ffg @ Wd  (BN=64 -> 160 blocks)
        {
            GBatch db{};
            db.p[0] = { ffg, wd, cat };
            mma_gemm_nn<128,64,32,32,true><<<dim3(16,10,1), 256>>>(db, FF, FF, DD, DD);
        }
    }
}